// round 5
// baseline (speedup 1.0000x reference)
#include <cuda_runtime.h>
#include <math_constants.h>

#define NN 25600
#define DEG 16
#define EE 409600
#define GB 8
#define FF 7
#define HH 300
#define LL 100
#define BK 20

typedef unsigned long long u64;

// ---- packed f32x2 helpers (PTX-only path; ptxas never auto-fuses FFMA2) ----
__device__ __forceinline__ u64 pack2(float x, float y) {
    u64 r;
    asm("mov.b64 %0, {%1, %2};" : "=l"(r) : "f"(x), "f"(y));
    return r;
}
__device__ __forceinline__ void ffma2(u64& d, u64 a, u64 b) {
    asm("fma.rn.f32x2 %0, %1, %2, %0;" : "+l"(d) : "l"(a), "l"(b));
}
__device__ __forceinline__ float2 unpack2(u64 v) {
    float2 r;
    asm("mov.b64 {%0, %1}, %2;" : "=f"(r.x), "=f"(r.y) : "l"(v));
    return r;
}

// ---------------- scratch (static device globals; no runtime allocation) ----
__device__ float g_P[NN * HH];              // per-node  x@(W1a-W1b)+b1
__device__ float g_Q[NN * HH];              // per-node  x@W1b
__device__ float g_node[NN * LL];           // per-node layer output (relu'd)
__device__ float g_pooled[GB * 3 * LL];     // [8, 300]

// ---- fused-kernel shared memory layout (dynamic) ----
// h2s : [300][132] float   at 0            (158400 B)  h2 tile, [k][row]
// As  : [20][132]  float   at 158400       (10560 B)   gathered A k-tile
// Bsp : [20][104]  u64     at 168960       (16640 B)   B k-tile, pre-duplicated pairs
// red : [32][104]  float   overlay at 158400 (epilogue only)
// src : [128]      int     at 185600       (512 B)
#define SM_H2   0
#define SM_AS   158400
#define SM_BSP  168960
#define SM_RED  158400
#define SM_SRC  185600
#define SM_TOTAL (185600 + 512)

// ---------------------------------------------------------------------------
// front: per-node first MLP layer, exploiting linearity of concat([x_i, x_j-x_i]).
// (scalar version — the FFMA2 variant regressed: packing movs + reg pressure)
__global__ void front_kernel(const float* __restrict__ xin, int K,
                             const float* __restrict__ W,
                             const float* __restrict__ b,
                             int from_node) {
    __shared__ float xs[16 * 100];
    const float* __restrict__ x = from_node ? g_node : xin;
    int n0 = blockIdx.x * 16;
    int j = threadIdx.x;  // 0..299
    for (int i = threadIdx.x; i < 16 * K; i += 300)
        xs[i] = x[n0 * K + i];
    __syncthreads();

    float accP[16], accQ[16];
    float bj = b[j];
#pragma unroll
    for (int r = 0; r < 16; r++) { accP[r] = bj; accQ[r] = 0.f; }

    for (int k = 0; k < K; k++) {
        float wa = W[k * HH + j];
        float wb = W[(K + k) * HH + j];
        float d = wa - wb;
#pragma unroll
        for (int r = 0; r < 16; r++) {
            float xv = xs[r * K + k];
            accP[r] = fmaf(xv, d, accP[r]);
            accQ[r] = fmaf(xv, wb, accQ[r]);
        }
    }
#pragma unroll
    for (int r = 0; r < 16; r++) {
        g_P[(n0 + r) * HH + j] = accP[r];
        g_Q[(n0 + r) * HH + j] = accQ[r];
    }
}

// ---------------------------------------------------------------------------
// fused edge layer: per CTA of 128 edges (= 8 nodes):
//   stage1: h2[128,300] = relu(relu(P[dst]+Q[src]) @ W2 + b2)  -> kept in smem
//   stage2: h3[128,100] = h2 @ W3 ; node out = relu(max16(h3) + b3)
// 640 threads: tx = tid%20 (5 cols, stride 20), ty = tid/20 (4 rows = 2 f32x2 pairs)
__global__ __launch_bounds__(640, 1) void fused_edge(const int* __restrict__ src,
                                                     const float* __restrict__ W2,
                                                     const float* __restrict__ b2,
                                                     const float* __restrict__ W3,
                                                     const float* __restrict__ b3) {
    extern __shared__ char sbuf[];
    float* h2s = (float*)(sbuf + SM_H2);
    float* As  = (float*)(sbuf + SM_AS);
    u64*   Bsp = (u64*)  (sbuf + SM_BSP);
    float* red = (float*)(sbuf + SM_RED);
    int* s_src = (int*)  (sbuf + SM_SRC);

    int tid = threadIdx.x;
    int tx = tid % 20, ty = tid / 20;
    int row0 = blockIdx.x * 128;
    int n0 = blockIdx.x * 8;

    if (tid < 128) s_src[tid] = src[row0 + tid];
    __syncthreads();

    // A gather task: one per thread
    int arow = tid / 5, akq = tid % 5;
    const float* Prow = g_P + (size_t)(n0 + (arow >> 4)) * HH + akq * 4;
    const float* Qrow = g_Q + (size_t)s_src[arow] * HH + akq * 4;
    // B fill task: tid<500
    int bk = tid / 25, bj = tid % 25;

    u64 acc[2][5];
    u64 z2 = pack2(0.f, 0.f);
#pragma unroll
    for (int i = 0; i < 2; i++)
#pragma unroll
        for (int j = 0; j < 5; j++) acc[i][j] = z2;

    // ---------- stage 1: 3 col-slabs x 15 k-tiles = 45 iterations ----------
    float4 pv = *(const float4*)&Prow[0];
    float4 qv = *(const float4*)&Qrow[0];
    float4 wv;
    if (tid < 500) wv = *(const float4*)&W2[bk * HH + bj * 4];

    for (int it = 0; it < 45; it++) {
        int slab = it / 15;
        int jt0 = slab * 100;
        // STS current tiles
        {
            float* a = &As[(akq * 4) * 132 + arow];
            a[0 * 132] = fmaxf(pv.x + qv.x, 0.f);
            a[1 * 132] = fmaxf(pv.y + qv.y, 0.f);
            a[2 * 132] = fmaxf(pv.z + qv.z, 0.f);
            a[3 * 132] = fmaxf(pv.w + qv.w, 0.f);
        }
        if (tid < 500) {
            u64* bp = &Bsp[bk * 104 + bj * 4];
            bp[0] = pack2(wv.x, wv.x);
            bp[1] = pack2(wv.y, wv.y);
            bp[2] = pack2(wv.z, wv.z);
            bp[3] = pack2(wv.w, wv.w);
        }
        __syncthreads();
        // prefetch next iteration (latency hidden under compute)
        if (it < 44) {
            int nit = it + 1;
            int nkt = (nit % 15) * BK;
            pv = *(const float4*)&Prow[nkt];
            qv = *(const float4*)&Qrow[nkt];
            if (tid < 500)
                wv = *(const float4*)&W2[(nkt + bk) * HH + (nit / 15) * 100 + bj * 4];
        }
        // compute
#pragma unroll
        for (int kk = 0; kk < BK; kk++) {
            ulonglong2 aa = *(const ulonglong2*)&As[kk * 132 + ty * 4];
            u64 b[5];
#pragma unroll
            for (int j = 0; j < 5; j++) b[j] = Bsp[kk * 104 + tx + 20 * j];
#pragma unroll
            for (int j = 0; j < 5; j++) {
                ffma2(acc[0][j], aa.x, b[j]);
                ffma2(acc[1][j], aa.y, b[j]);
            }
        }
        // slab epilogue: commit h2 slab to smem, reset acc
        if (it % 15 == 14) {
#pragma unroll
            for (int j = 0; j < 5; j++) {
                int col = jt0 + tx + 20 * j;
                float bb = b2[col];
                float2 v0 = unpack2(acc[0][j]);
                float2 v1 = unpack2(acc[1][j]);
                float4 o;
                o.x = fmaxf(v0.x + bb, 0.f);
                o.y = fmaxf(v0.y + bb, 0.f);
                o.z = fmaxf(v1.x + bb, 0.f);
                o.w = fmaxf(v1.y + bb, 0.f);
                *(float4*)&h2s[col * 132 + ty * 4] = o;
                acc[0][j] = z2;
                acc[1][j] = z2;
            }
        }
        __syncthreads();
    }

    // ---------- stage 2: h2s @ W3, 15 k-tiles, A straight from smem ----------
    if (tid < 500) wv = *(const float4*)&W3[bk * LL + bj * 4];
    for (int kt = 0; kt < 15; kt++) {
        if (tid < 500) {
            u64* bp = &Bsp[bk * 104 + bj * 4];
            bp[0] = pack2(wv.x, wv.x);
            bp[1] = pack2(wv.y, wv.y);
            bp[2] = pack2(wv.z, wv.z);
            bp[3] = pack2(wv.w, wv.w);
        }
        __syncthreads();
        if (kt < 14 && tid < 500)
            wv = *(const float4*)&W3[((kt + 1) * BK + bk) * LL + bj * 4];
#pragma unroll
        for (int kk = 0; kk < BK; kk++) {
            ulonglong2 aa = *(const ulonglong2*)&h2s[(kt * BK + kk) * 132 + ty * 4];
            u64 b[5];
#pragma unroll
            for (int j = 0; j < 5; j++) b[j] = Bsp[kk * 104 + tx + 20 * j];
#pragma unroll
            for (int j = 0; j < 5; j++) {
                ffma2(acc[0][j], aa.x, b[j]);
                ffma2(acc[1][j], aa.y, b[j]);
            }
        }
        __syncthreads();
    }

    // ---------- epilogue: max over 16-edge groups, +b3, relu ----------
#pragma unroll
    for (int j = 0; j < 5; j++) {
        float2 v0 = unpack2(acc[0][j]);
        float2 v1 = unpack2(acc[1][j]);
        red[ty * 104 + tx + 20 * j] =
            fmaxf(fmaxf(v0.x, v0.y), fmaxf(v1.x, v1.y));
    }
    __syncthreads();
    for (int t = tid; t < 800; t += 640) {
        int n = t / 100, c = t % 100;
        const float* r = &red[(4 * n) * 104 + c];
        float m = fmaxf(fmaxf(r[0], r[104]), fmaxf(r[208], r[312]));
        g_node[(n0 + n) * LL + c] = fmaxf(m + b3[c], 0.f);
    }
}

// ---------------------------------------------------------------------------
// pool: per-graph (3200 consecutive nodes) sum / mean / max over g_node[N,100]
__global__ void pool_kernel() {
    __shared__ float ssum[8][100];
    __shared__ float smax[8][100];
    int g = blockIdx.x;
    int col = threadIdx.x % 100;
    int part = threadIdx.x / 100;
    float s = 0.f, m = -CUDART_INF_F;
    int base = g * 3200 + part * 400;
    for (int n = 0; n < 400; n++) {
        float v = g_node[(base + n) * LL + col];
        s += v;
        m = fmaxf(m, v);
    }
    ssum[part][col] = s;
    smax[part][col] = m;
    __syncthreads();
    if (part == 0) {
        for (int p = 1; p < 8; p++) {
            s += ssum[p][col];
            m = fmaxf(m, smax[p][col]);
        }
        g_pooled[g * 300 + col] = s;
        g_pooled[g * 300 + 100 + col] = s / 3200.0f;
        g_pooled[g * 300 + 200 + col] = m;
    }
}

// ---------------------------------------------------------------------------
// head MLP: [8,300] -> relu 100 -> relu 100 -> 1. One block, 128 threads.
__global__ void final_kernel(const float* __restrict__ W1, const float* __restrict__ b1,
                             const float* __restrict__ W2, const float* __restrict__ b2,
                             const float* __restrict__ W3, const float* __restrict__ b3,
                             float* __restrict__ out) {
    __shared__ float sp[GB * 300];
    __shared__ float t1[GB * 100];
    int j = threadIdx.x;
    for (int i = j; i < GB * 300; i += blockDim.x) sp[i] = g_pooled[i];
    __syncthreads();

    if (j < 100) {
        float acc[GB];
#pragma unroll
        for (int r = 0; r < GB; r++) acc[r] = b1[j];
        for (int k = 0; k < 300; k++) {
            float w = W1[k * 100 + j];
#pragma unroll
            for (int r = 0; r < GB; r++) acc[r] = fmaf(sp[r * 300 + k], w, acc[r]);
        }
#pragma unroll
        for (int r = 0; r < GB; r++) t1[r * 100 + j] = fmaxf(acc[r], 0.f);
    }
    __syncthreads();

    float acc2[GB];
    if (j < 100) {
#pragma unroll
        for (int r = 0; r < GB; r++) acc2[r] = b2[j];
        for (int k = 0; k < 100; k++) {
            float w = W2[k * 100 + j];
#pragma unroll
            for (int r = 0; r < GB; r++) acc2[r] = fmaf(t1[r * 100 + k], w, acc2[r]);
        }
    }
    __syncthreads();
    if (j < 100) {
#pragma unroll
        for (int r = 0; r < GB; r++) sp[r * 100 + j] = fmaxf(acc2[r], 0.f);
    }
    __syncthreads();

    if (j < GB) {
        float s = b3[0];
        for (int k = 0; k < 100; k++) s = fmaf(sp[j * 100 + k], W3[k], s);
        out[j] = s;
    }
}

// ---------------------------------------------------------------------------
extern "C" void kernel_launch(void* const* d_in, const int* in_sizes, int n_in,
                              void* d_out, int out_size) {
    const float* x        = (const float*)d_in[0];
    const int*   eidx     = (const int*)d_in[1];   // [2,E]: row0=src, row1=dst
    const float* l0_W1 = (const float*)d_in[3];
    const float* l0_b1 = (const float*)d_in[4];
    const float* l0_W2 = (const float*)d_in[5];
    const float* l0_b2 = (const float*)d_in[6];
    const float* l0_W3 = (const float*)d_in[7];
    const float* l0_b3 = (const float*)d_in[8];
    const float* l1_W1 = (const float*)d_in[9];
    const float* l1_b1 = (const float*)d_in[10];
    const float* l1_W2 = (const float*)d_in[11];
    const float* l1_b2 = (const float*)d_in[12];
    const float* l1_W3 = (const float*)d_in[13];
    const float* l1_b3 = (const float*)d_in[14];
    const float* lin_W1 = (const float*)d_in[15];
    const float* lin_b1 = (const float*)d_in[16];
    const float* lin_W2 = (const float*)d_in[17];
    const float* lin_b2 = (const float*)d_in[18];
    const float* lin_W3 = (const float*)d_in[19];
    const float* lin_b3 = (const float*)d_in[20];

    const int* src = eidx;  // first row of edge_index

    cudaFuncSetAttribute(fused_edge, cudaFuncAttributeMaxDynamicSharedMemorySize,
                         SM_TOTAL);

    // ---- layer 0 ----
    front_kernel<<<NN / 16, 300>>>(x, FF, l0_W1, l0_b1, 0);
    fused_edge<<<EE / 128, 640, SM_TOTAL>>>(src, l0_W2, l0_b2, l0_W3, l0_b3);
    // ---- layer 1 ----
    front_kernel<<<NN / 16, 300>>>(nullptr, LL, l1_W1, l1_b1, 1);
    fused_edge<<<EE / 128, 640, SM_TOTAL>>>(src, l1_W2, l1_b2, l1_W3, l1_b3);
    // ---- pooling + head ----
    pool_kernel<<<GB, 800>>>();
    final_kernel<<<1, 128>>>(lin_W1, lin_b1, lin_W2, lin_b2, lin_W3, lin_b3,
                             (float*)d_out);
}

// round 7
// speedup vs baseline: 1.6202x; 1.6202x over previous
#include <cuda_runtime.h>
#include <math_constants.h>

#define NN 25600
#define DEG 16
#define EE 409600
#define GB 8
#define FF 7
#define HH 300
#define LL 100
#define BK 20

typedef unsigned long long u64;

// ---- packed f32x2 helpers (PTX-only path; ptxas never auto-fuses FFMA2) ----
__device__ __forceinline__ u64 pack2(float x, float y) {
    u64 r;
    asm("mov.b64 %0, {%1, %2};" : "=l"(r) : "f"(x), "f"(y));
    return r;
}
__device__ __forceinline__ void ffma2(u64& d, u64 a, u64 b) {
    asm("fma.rn.f32x2 %0, %1, %2, %0;" : "+l"(d) : "l"(a), "l"(b));
}
__device__ __forceinline__ float2 unpack2(u64 v) {
    float2 r;
    asm("mov.b64 {%0, %1}, %2;" : "=f"(r.x), "=f"(r.y) : "l"(v));
    return r;
}

// ---------------- scratch (static device globals; no runtime allocation) ----
__device__ float g_P[NN * HH];              // per-node  x@(W1a-W1b)+b1
__device__ float g_Q[NN * HH];              // per-node  x@W1b
__device__ float g_h2[EE * (size_t)HH];     // per-edge hidden (491.5 MB)
__device__ float g_node[NN * LL];           // per-node layer output (relu'd)
__device__ float g_pooled[GB * 3 * LL];     // [8, 300]

// ---------------------------------------------------------------------------
// front: per-node first MLP layer, exploiting linearity of concat([x_i, x_j-x_i]).
// (scalar version — packed variant regressed: marshaling movs + reg pressure)
__global__ void front_kernel(const float* __restrict__ xin, int K,
                             const float* __restrict__ W,
                             const float* __restrict__ b,
                             int from_node) {
    __shared__ float xs[16 * 100];
    const float* __restrict__ x = from_node ? g_node : xin;
    int n0 = blockIdx.x * 16;
    int j = threadIdx.x;  // 0..299
    for (int i = threadIdx.x; i < 16 * K; i += 300)
        xs[i] = x[n0 * K + i];
    __syncthreads();

    float accP[16], accQ[16];
    float bj = b[j];
#pragma unroll
    for (int r = 0; r < 16; r++) { accP[r] = bj; accQ[r] = 0.f; }

    for (int k = 0; k < K; k++) {
        float wa = W[k * HH + j];
        float wb = W[(K + k) * HH + j];
        float d = wa - wb;
#pragma unroll
        for (int r = 0; r < 16; r++) {
            float xv = xs[r * K + k];
            accP[r] = fmaf(xv, d, accP[r]);
            accQ[r] = fmaf(xv, wb, accQ[r]);
        }
    }
#pragma unroll
    for (int r = 0; r < 16; r++) {
        g_P[(n0 + r) * HH + j] = accP[r];
        g_Q[(n0 + r) * HH + j] = accQ[r];
    }
}

// ---------------------------------------------------------------------------
// gemm_mid: h2[e, col] = relu( relu(P[e/16]+Q[src[e]]) @ W2 + b2 )
// Tile BM=128 edges x BN=100 cols, BK=20. 320 threads, m=8 (4 f32x2 pairs) x n=5.
// B pre-duplicated in smem as u64 pairs (no per-kk pack movs); global loads
// register double-buffered (prefetch next k-tile under compute).
__global__ __launch_bounds__(320, 2) void gemm_mid(const int* __restrict__ src,
                                                   const float* __restrict__ W,
                                                   const float* __restrict__ bias) {
    __shared__ __align__(16) float As[BK][132];
    __shared__ __align__(16) u64 Bsp[BK][104];
    __shared__ int s_src[128];

    int tid = threadIdx.x;
    int tx = tid % 20, ty = tid / 20;
    int row0 = blockIdx.y * 128;
    int n0 = blockIdx.y * 8;
    int jt0 = blockIdx.x * 100;

    if (tid < 128) s_src[tid] = src[row0 + tid];
    __syncthreads();

    // A tasks (640 float4-pairs over 320 threads => 2 each)
    int r1 = tid / 5, k1 = (tid % 5) * 4;
    int r2 = (tid + 320) / 5, k2 = ((tid + 320) % 5) * 4;
    const float* P1 = &g_P[(size_t)(n0 + (r1 >> 4)) * HH + k1];
    const float* Q1 = &g_Q[(size_t)s_src[r1] * HH + k1];
    const float* P2 = &g_P[(size_t)(n0 + (r2 >> 4)) * HH + k2];
    const float* Q2 = &g_Q[(size_t)s_src[r2] * HH + k2];
    // B tasks (500 float4 over 320 threads)
    int bk1 = tid / 25, bj1 = (tid % 25) * 4;
    int bk2 = (tid + 320) / 25, bj2 = ((tid + 320) % 25) * 4;

    u64 acc[4][5];
    u64 z2 = pack2(0.f, 0.f);
#pragma unroll
    for (int i = 0; i < 4; i++)
#pragma unroll
        for (int j = 0; j < 5; j++) acc[i][j] = z2;

    // prologue: load k-tile 0 into registers
    float4 pv1 = *(const float4*)&P1[0];
    float4 qv1 = *(const float4*)&Q1[0];
    float4 pv2 = *(const float4*)&P2[0];
    float4 qv2 = *(const float4*)&Q2[0];
    float4 wv1, wv2;
    if (tid < 500) wv1 = *(const float4*)&W[bk1 * HH + jt0 + bj1];
    if (tid < 180) wv2 = *(const float4*)&W[bk2 * HH + jt0 + bj2];

    for (int kt = 0; kt < 15; kt++) {
        // commit prefetched tile to smem
        As[k1 + 0][r1] = fmaxf(pv1.x + qv1.x, 0.f);
        As[k1 + 1][r1] = fmaxf(pv1.y + qv1.y, 0.f);
        As[k1 + 2][r1] = fmaxf(pv1.z + qv1.z, 0.f);
        As[k1 + 3][r1] = fmaxf(pv1.w + qv1.w, 0.f);
        As[k2 + 0][r2] = fmaxf(pv2.x + qv2.x, 0.f);
        As[k2 + 1][r2] = fmaxf(pv2.y + qv2.y, 0.f);
        As[k2 + 2][r2] = fmaxf(pv2.z + qv2.z, 0.f);
        As[k2 + 3][r2] = fmaxf(pv2.w + qv2.w, 0.f);
        if (tid < 500) {
            Bsp[bk1][bj1 + 0] = pack2(wv1.x, wv1.x);
            Bsp[bk1][bj1 + 1] = pack2(wv1.y, wv1.y);
            Bsp[bk1][bj1 + 2] = pack2(wv1.z, wv1.z);
            Bsp[bk1][bj1 + 3] = pack2(wv1.w, wv1.w);
        }
        if (tid < 180) {
            Bsp[bk2][bj2 + 0] = pack2(wv2.x, wv2.x);
            Bsp[bk2][bj2 + 1] = pack2(wv2.y, wv2.y);
            Bsp[bk2][bj2 + 2] = pack2(wv2.z, wv2.z);
            Bsp[bk2][bj2 + 3] = pack2(wv2.w, wv2.w);
        }
        __syncthreads();
        // prefetch next k-tile (latency hidden under compute below)
        if (kt < 14) {
            int kn = (kt + 1) * BK;
            pv1 = *(const float4*)&P1[kn];
            qv1 = *(const float4*)&Q1[kn];
            pv2 = *(const float4*)&P2[kn];
            qv2 = *(const float4*)&Q2[kn];
            if (tid < 500) wv1 = *(const float4*)&W[(kn + bk1) * HH + jt0 + bj1];
            if (tid < 180) wv2 = *(const float4*)&W[(kn + bk2) * HH + jt0 + bj2];
        }
        // compute
#pragma unroll
        for (int kk = 0; kk < BK; kk++) {
            ulonglong2 aA = *(const ulonglong2*)&As[kk][ty * 8];
            ulonglong2 aB = *(const ulonglong2*)&As[kk][ty * 8 + 4];
            u64 b[5];
#pragma unroll
            for (int j = 0; j < 5; j++) b[j] = Bsp[kk][tx + 20 * j];
#pragma unroll
            for (int j = 0; j < 5; j++) {
                ffma2(acc[0][j], aA.x, b[j]);
                ffma2(acc[1][j], aA.y, b[j]);
                ffma2(acc[2][j], aB.x, b[j]);
                ffma2(acc[3][j], aB.y, b[j]);
            }
        }
        __syncthreads();
    }

#pragma unroll
    for (int j = 0; j < 5; j++) {
        int col = jt0 + tx + 20 * j;
        float bb = bias[col];
#pragma unroll
        for (int i = 0; i < 4; i++) {
            float2 v = unpack2(acc[i][j]);
            int row = row0 + ty * 8 + 2 * i;
            g_h2[(size_t)row * HH + col] = fmaxf(v.x + bb, 0.f);
            g_h2[(size_t)(row + 1) * HH + col] = fmaxf(v.y + bb, 0.f);
        }
    }
}

// ---------------------------------------------------------------------------
// gemm_out: h3 = h2 @ W3 + b3 [E,100], fused max over 16-row groups + relu
//   -> g_node[n, col] = relu( max_{e in node n} h3[e,col] + b3[col] )
__global__ __launch_bounds__(320, 2) void gemm_out(const float* __restrict__ W,
                                                   const float* __restrict__ bias) {
    __shared__ __align__(16) float As[BK][132];
    __shared__ __align__(16) u64 Bsp[BK][104];
    __shared__ float red[16][100];

    int tid = threadIdx.x;
    int tx = tid % 20, ty = tid / 20;
    int row0 = blockIdx.x * 128;
    int n0 = blockIdx.x * 8;

    int r1 = tid / 5, k1 = (tid % 5) * 4;
    int r2 = (tid + 320) / 5, k2 = ((tid + 320) % 5) * 4;
    const float* A1 = &g_h2[(size_t)(row0 + r1) * HH + k1];
    const float* A2 = &g_h2[(size_t)(row0 + r2) * HH + k2];
    int bk1 = tid / 25, bj1 = (tid % 25) * 4;
    int bk2 = (tid + 320) / 25, bj2 = ((tid + 320) % 25) * 4;

    u64 acc[4][5];
    u64 z2 = pack2(0.f, 0.f);
#pragma unroll
    for (int i = 0; i < 4; i++)
#pragma unroll
        for (int j = 0; j < 5; j++) acc[i][j] = z2;

    float4 av1 = *(const float4*)&A1[0];
    float4 av2 = *(const float4*)&A2[0];
    float4 wv1, wv2;
    if (tid < 500) wv1 = *(const float4*)&W[bk1 * LL + bj1];
    if (tid < 180) wv2 = *(const float4*)&W[bk2 * LL + bj2];

    for (int kt = 0; kt < 15; kt++) {
        As[k1 + 0][r1] = av1.x;
        As[k1 + 1][r1] = av1.y;
        As[k1 + 2][r1] = av1.z;
        As[k1 + 3][r1] = av1.w;
        As[k2 + 0][r2] = av2.x;
        As[k2 + 1][r2] = av2.y;
        As[k2 + 2][r2] = av2.z;
        As[k2 + 3][r2] = av2.w;
        if (tid < 500) {
            Bsp[bk1][bj1 + 0] = pack2(wv1.x, wv1.x);
            Bsp[bk1][bj1 + 1] = pack2(wv1.y, wv1.y);
            Bsp[bk1][bj1 + 2] = pack2(wv1.z, wv1.z);
            Bsp[bk1][bj1 + 3] = pack2(wv1.w, wv1.w);
        }
        if (tid < 180) {
            Bsp[bk2][bj2 + 0] = pack2(wv2.x, wv2.x);
            Bsp[bk2][bj2 + 1] = pack2(wv2.y, wv2.y);
            Bsp[bk2][bj2 + 2] = pack2(wv2.z, wv2.z);
            Bsp[bk2][bj2 + 3] = pack2(wv2.w, wv2.w);
        }
        __syncthreads();
        if (kt < 14) {
            int kn = (kt + 1) * BK;
            av1 = *(const float4*)&A1[kn];
            av2 = *(const float4*)&A2[kn];
            if (tid < 500) wv1 = *(const float4*)&W[(kn + bk1) * LL + bj1];
            if (tid < 180) wv2 = *(const float4*)&W[(kn + bk2) * LL + bj2];
        }
#pragma unroll
        for (int kk = 0; kk < BK; kk++) {
            ulonglong2 aA = *(const ulonglong2*)&As[kk][ty * 8];
            ulonglong2 aB = *(const ulonglong2*)&As[kk][ty * 8 + 4];
            u64 b[5];
#pragma unroll
            for (int j = 0; j < 5; j++) b[j] = Bsp[kk][tx + 20 * j];
#pragma unroll
            for (int j = 0; j < 5; j++) {
                ffma2(acc[0][j], aA.x, b[j]);
                ffma2(acc[1][j], aA.y, b[j]);
                ffma2(acc[2][j], aB.x, b[j]);
                ffma2(acc[3][j], aB.y, b[j]);
            }
        }
        __syncthreads();
    }

    // thread-local max over its 8 contiguous rows (half a 16-edge node group)
#pragma unroll
    for (int j = 0; j < 5; j++) {
        int col = tx + 20 * j;
        float2 v0 = unpack2(acc[0][j]);
        float2 v1 = unpack2(acc[1][j]);
        float2 v2 = unpack2(acc[2][j]);
        float2 v3 = unpack2(acc[3][j]);
        float m = fmaxf(fmaxf(fmaxf(v0.x, v0.y), fmaxf(v1.x, v1.y)),
                        fmaxf(fmaxf(v2.x, v2.y), fmaxf(v3.x, v3.y)));
        red[ty][col] = m;
    }
    __syncthreads();
    if (ty < 8) {
#pragma unroll
        for (int j = 0; j < 5; j++) {
            int col = tx + 20 * j;
            float m = fmaxf(red[2 * ty][col], red[2 * ty + 1][col]);
            g_node[(n0 + ty) * LL + col] = fmaxf(m + bias[col], 0.f);
        }
    }
}

// ---------------------------------------------------------------------------
// pool: per-graph (3200 consecutive nodes) sum / mean / max over g_node[N,100]
__global__ void pool_kernel() {
    __shared__ float ssum[8][100];
    __shared__ float smax[8][100];
    int g = blockIdx.x;
    int col = threadIdx.x % 100;
    int part = threadIdx.x / 100;
    float s = 0.f, m = -CUDART_INF_F;
    int base = g * 3200 + part * 400;
    for (int n = 0; n < 400; n++) {
        float v = g_node[(base + n) * LL + col];
        s += v;
        m = fmaxf(m, v);
    }
    ssum[part][col] = s;
    smax[part][col] = m;
    __syncthreads();
    if (part == 0) {
        for (int p = 1; p < 8; p++) {
            s += ssum[p][col];
            m = fmaxf(m, smax[p][col]);
        }
        g_pooled[g * 300 + col] = s;
        g_pooled[g * 300 + 100 + col] = s / 3200.0f;
        g_pooled[g * 300 + 200 + col] = m;
    }
}

// ---------------------------------------------------------------------------
// head MLP: [8,300] -> relu 100 -> relu 100 -> 1. One block, 128 threads.
__global__ void final_kernel(const float* __restrict__ W1, const float* __restrict__ b1,
                             const float* __restrict__ W2, const float* __restrict__ b2,
                             const float* __restrict__ W3, const float* __restrict__ b3,
                             float* __restrict__ out) {
    __shared__ float sp[GB * 300];
    __shared__ float t1[GB * 100];
    int j = threadIdx.x;
    for (int i = j; i < GB * 300; i += blockDim.x) sp[i] = g_pooled[i];
    __syncthreads();

    if (j < 100) {
        float acc[GB];
#pragma unroll
        for (int r = 0; r < GB; r++) acc[r] = b1[j];
        for (int k = 0; k < 300; k++) {
            float w = W1[k * 100 + j];
#pragma unroll
            for (int r = 0; r < GB; r++) acc[r] = fmaf(sp[r * 300 + k], w, acc[r]);
        }
#pragma unroll
        for (int r = 0; r < GB; r++) t1[r * 100 + j] = fmaxf(acc[r], 0.f);
    }
    __syncthreads();

    float acc2[GB];
    if (j < 100) {
#pragma unroll
        for (int r = 0; r < GB; r++) acc2[r] = b2[j];
        for (int k = 0; k < 100; k++) {
            float w = W2[k * 100 + j];
#pragma unroll
            for (int r = 0; r < GB; r++) acc2[r] = fmaf(t1[r * 100 + k], w, acc2[r]);
        }
    }
    __syncthreads();
    if (j < 100) {
#pragma unroll
        for (int r = 0; r < GB; r++) sp[r * 100 + j] = fmaxf(acc2[r], 0.f);
    }
    __syncthreads();

    if (j < GB) {
        float s = b3[0];
        for (int k = 0; k < 100; k++) s = fmaf(sp[j * 100 + k], W3[k], s);
        out[j] = s;
    }
}

// ---------------------------------------------------------------------------
extern "C" void kernel_launch(void* const* d_in, const int* in_sizes, int n_in,
                              void* d_out, int out_size) {
    const float* x        = (const float*)d_in[0];
    const int*   eidx     = (const int*)d_in[1];   // [2,E]: row0=src, row1=dst
    const float* l0_W1 = (const float*)d_in[3];
    const float* l0_b1 = (const float*)d_in[4];
    const float* l0_W2 = (const float*)d_in[5];
    const float* l0_b2 = (const float*)d_in[6];
    const float* l0_W3 = (const float*)d_in[7];
    const float* l0_b3 = (const float*)d_in[8];
    const float* l1_W1 = (const float*)d_in[9];
    const float* l1_b1 = (const float*)d_in[10];
    const float* l1_W2 = (const float*)d_in[11];
    const float* l1_b2 = (const float*)d_in[12];
    const float* l1_W3 = (const float*)d_in[13];
    const float* l1_b3 = (const float*)d_in[14];
    const float* lin_W1 = (const float*)d_in[15];
    const float* lin_b1 = (const float*)d_in[16];
    const float* lin_W2 = (const float*)d_in[17];
    const float* lin_b2 = (const float*)d_in[18];
    const float* lin_W3 = (const float*)d_in[19];
    const float* lin_b3 = (const float*)d_in[20];

    const int* src = eidx;  // first row of edge_index

    // ---- layer 0 ----
    front_kernel<<<NN / 16, 300>>>(x, FF, l0_W1, l0_b1, 0);
    gemm_mid<<<dim3(3, EE / 128), 320>>>(src, l0_W2, l0_b2);
    gemm_out<<<EE / 128, 320>>>(l0_W3, l0_b3);
    // ---- layer 1 ----
    front_kernel<<<NN / 16, 300>>>(nullptr, LL, l1_W1, l1_b1, 1);
    gemm_mid<<<dim3(3, EE / 128), 320>>>(src, l1_W2, l1_b2);
    gemm_out<<<EE / 128, 320>>>(l1_W3, l1_b3);
    // ---- pooling + head ----
    pool_kernel<<<GB, 800>>>();
    final_kernel<<<1, 128>>>(lin_W1, lin_b1, lin_W2, lin_b2, lin_W3, lin_b3,
                             (float*)d_out);
}

// round 8
// speedup vs baseline: 2.3341x; 1.4406x over previous
#include <cuda_runtime.h>
#include <math_constants.h>

#define NN 25600
#define DEG 16
#define EE 409600
#define GB 8
#define FF 7
#define HH 300
#define LL 100
#define BK 20

typedef unsigned long long u64;

// ---- packed f32x2 helpers (PTX-only path; ptxas never auto-fuses FFMA2) ----
__device__ __forceinline__ u64 pack2(float x, float y) {
    u64 r;
    asm("mov.b64 %0, {%1, %2};" : "=l"(r) : "f"(x), "f"(y));
    return r;
}
__device__ __forceinline__ void ffma2(u64& d, u64 a, u64 b) {
    asm("fma.rn.f32x2 %0, %1, %2, %0;" : "+l"(d) : "l"(a), "l"(b));
}
__device__ __forceinline__ float2 unpack2(u64 v) {
    float2 r;
    asm("mov.b64 {%0, %1}, %2;" : "=f"(r.x), "=f"(r.y) : "l"(v));
    return r;
}

// ---- cp.async helpers (global->shared, 16B, zero register cost) ----
__device__ __forceinline__ unsigned smem_u32(const void* p) {
    unsigned a;
    asm("{ .reg .u64 t; cvta.to.shared.u64 t, %1; cvt.u32.u64 %0, t; }"
        : "=r"(a) : "l"(p));
    return a;
}
__device__ __forceinline__ void cpa16(unsigned dst, const void* src) {
    asm volatile("cp.async.cg.shared.global [%0], [%1], 16;" :: "r"(dst), "l"(src));
}
__device__ __forceinline__ void cpa_commit() {
    asm volatile("cp.async.commit_group;");
}
__device__ __forceinline__ void cpa_wait1() {
    asm volatile("cp.async.wait_group 1;");
}
__device__ __forceinline__ void cpa_wait0() {
    asm volatile("cp.async.wait_group 0;");
}

// ---------------- scratch (static device globals; no runtime allocation) ----
__device__ float g_P[NN * HH];              // per-node  x@(W1a-W1b)+b1
__device__ float g_Q[NN * HH];              // per-node  x@W1b
__device__ float g_h2[EE * (size_t)HH];     // per-edge hidden (491.5 MB)
__device__ float g_node[NN * LL];           // per-node layer output (relu'd)
__device__ float g_pooled[GB * 3 * LL];     // [8, 300]

// ---------------------------------------------------------------------------
// front: per-node first MLP layer, exploiting linearity of concat([x_i, x_j-x_i]).
__global__ void front_kernel(const float* __restrict__ xin, int K,
                             const float* __restrict__ W,
                             const float* __restrict__ b,
                             int from_node) {
    __shared__ float xs[16 * 100];
    const float* __restrict__ x = from_node ? g_node : xin;
    int n0 = blockIdx.x * 16;
    int j = threadIdx.x;  // 0..299
    for (int i = threadIdx.x; i < 16 * K; i += 300)
        xs[i] = x[n0 * K + i];
    __syncthreads();

    float accP[16], accQ[16];
    float bj = b[j];
#pragma unroll
    for (int r = 0; r < 16; r++) { accP[r] = bj; accQ[r] = 0.f; }

    for (int k = 0; k < K; k++) {
        float wa = W[k * HH + j];
        float wb = W[(K + k) * HH + j];
        float d = wa - wb;
#pragma unroll
        for (int r = 0; r < 16; r++) {
            float xv = xs[r * K + k];
            accP[r] = fmaf(xv, d, accP[r]);
            accQ[r] = fmaf(xv, wb, accQ[r]);
        }
    }
#pragma unroll
    for (int r = 0; r < 16; r++) {
        g_P[(n0 + r) * HH + j] = accP[r];
        g_Q[(n0 + r) * HH + j] = accQ[r];
    }
}

// ---------------------------------------------------------------------------
// gemm_mid: h2[e, col] = relu( relu(P[e/16]+Q[src[e]]) @ W2 + b2 )
// R4 inner loop (scalar B + per-kk pack2, m=8 x n=5 FFMA2) + cp.async
// double-buffered B tiles + register-prefetched A tiles.
__global__ __launch_bounds__(320, 2) void gemm_mid(const int* __restrict__ src,
                                                   const float* __restrict__ W,
                                                   const float* __restrict__ bias) {
    __shared__ __align__(16) float As[BK][132];
    __shared__ __align__(16) float Bs[2][BK][104];
    __shared__ int s_src[128];

    int tid = threadIdx.x;
    int tx = tid % 20, ty = tid / 20;
    int row0 = blockIdx.y * 128;
    int n0 = blockIdx.y * 8;
    int jt0 = blockIdx.x * 100;

    if (tid < 128) s_src[tid] = src[row0 + tid];
    __syncthreads();

    // A gather tasks (640 float4-pairs over 320 threads => 2 each)
    int r1 = tid / 5, k1 = (tid % 5) * 4;
    int r2 = (tid + 320) / 5, k2 = ((tid + 320) % 5) * 4;
    const float* P1 = &g_P[(size_t)(n0 + (r1 >> 4)) * HH + k1];
    const float* Q1 = &g_Q[(size_t)s_src[r1] * HH + k1];
    const float* P2 = &g_P[(size_t)(n0 + (r2 >> 4)) * HH + k2];
    const float* Q2 = &g_Q[(size_t)s_src[r2] * HH + k2];
    // B cp.async tasks (500 x 16B over 320 threads)
    int bk1 = tid / 25, bj1 = (tid % 25) * 4;
    int bk2 = (tid + 320) / 25, bj2 = ((tid + 320) % 25) * 4;
    unsigned d1b0 = smem_u32(&Bs[0][bk1][bj1]);
    unsigned d1b1 = smem_u32(&Bs[1][bk1][bj1]);
    unsigned d2b0 = smem_u32(&Bs[0][bk2][bj2]);
    unsigned d2b1 = smem_u32(&Bs[1][bk2][bj2]);

    u64 acc[4][5];
    u64 z2 = pack2(0.f, 0.f);
#pragma unroll
    for (int i = 0; i < 4; i++)
#pragma unroll
        for (int j = 0; j < 5; j++) acc[i][j] = z2;

    // prologue: B(0) via cp.async, A(0) into registers
    cpa16(d1b0, &W[bk1 * HH + jt0 + bj1]);
    if (tid < 180) cpa16(d2b0, &W[bk2 * HH + jt0 + bj2]);
    cpa_commit();
    float4 pv1 = *(const float4*)&P1[0];
    float4 qv1 = *(const float4*)&Q1[0];
    float4 pv2 = *(const float4*)&P2[0];
    float4 qv2 = *(const float4*)&Q2[0];

    for (int kt = 0; kt < 15; kt++) {
        int cur = kt & 1;
        // issue B(kt+1) into the other buffer, then wait for B(kt)
        if (kt < 14) {
            int kn = (kt + 1) * BK;
            cpa16(cur ? d1b0 : d1b1, &W[(kn + bk1) * HH + jt0 + bj1]);
            if (tid < 180) cpa16(cur ? d2b0 : d2b1, &W[(kn + bk2) * HH + jt0 + bj2]);
            cpa_commit();
            cpa_wait1();
        } else {
            cpa_wait0();
        }
        // commit prefetched A tile to smem
        As[k1 + 0][r1] = fmaxf(pv1.x + qv1.x, 0.f);
        As[k1 + 1][r1] = fmaxf(pv1.y + qv1.y, 0.f);
        As[k1 + 2][r1] = fmaxf(pv1.z + qv1.z, 0.f);
        As[k1 + 3][r1] = fmaxf(pv1.w + qv1.w, 0.f);
        As[k2 + 0][r2] = fmaxf(pv2.x + qv2.x, 0.f);
        As[k2 + 1][r2] = fmaxf(pv2.y + qv2.y, 0.f);
        As[k2 + 2][r2] = fmaxf(pv2.z + qv2.z, 0.f);
        As[k2 + 3][r2] = fmaxf(pv2.w + qv2.w, 0.f);
        __syncthreads();
        // prefetch A(kt+1) into registers (hidden under compute)
        if (kt < 14) {
            int kn = (kt + 1) * BK;
            pv1 = *(const float4*)&P1[kn];
            qv1 = *(const float4*)&Q1[kn];
            pv2 = *(const float4*)&P2[kn];
            qv2 = *(const float4*)&Q2[kn];
        }
        // compute (identical to R4)
#pragma unroll
        for (int kk = 0; kk < BK; kk++) {
            ulonglong2 aA = *(const ulonglong2*)&As[kk][ty * 8];
            ulonglong2 aB = *(const ulonglong2*)&As[kk][ty * 8 + 4];
            u64 b[5];
#pragma unroll
            for (int j = 0; j < 5; j++) {
                float bv = Bs[cur][kk][tx + 20 * j];
                b[j] = pack2(bv, bv);
            }
#pragma unroll
            for (int j = 0; j < 5; j++) {
                ffma2(acc[0][j], aA.x, b[j]);
                ffma2(acc[1][j], aA.y, b[j]);
                ffma2(acc[2][j], aB.x, b[j]);
                ffma2(acc[3][j], aB.y, b[j]);
            }
        }
        __syncthreads();
    }

#pragma unroll
    for (int j = 0; j < 5; j++) {
        int col = jt0 + tx + 20 * j;
        float bb = bias[col];
#pragma unroll
        for (int i = 0; i < 4; i++) {
            float2 v = unpack2(acc[i][j]);
            int row = row0 + ty * 8 + 2 * i;
            g_h2[(size_t)row * HH + col] = fmaxf(v.x + bb, 0.f);
            g_h2[(size_t)(row + 1) * HH + col] = fmaxf(v.y + bb, 0.f);
        }
    }
}

// ---------------------------------------------------------------------------
// gemm_out: h3 = h2 @ W3 + b3 [E,100], fused max over 16-row groups + relu
//   -> g_node[n, col] = relu( max_{e in node n} h3[e,col] + b3[col] )
__global__ __launch_bounds__(320, 2) void gemm_out(const float* __restrict__ W,
                                                   const float* __restrict__ bias) {
    __shared__ __align__(16) float As[BK][132];
    __shared__ __align__(16) float Bs[2][BK][104];
    __shared__ float red[16][100];

    int tid = threadIdx.x;
    int tx = tid % 20, ty = tid / 20;
    int row0 = blockIdx.x * 128;
    int n0 = blockIdx.x * 8;

    int r1 = tid / 5, k1 = (tid % 5) * 4;
    int r2 = (tid + 320) / 5, k2 = ((tid + 320) % 5) * 4;
    const float* A1 = &g_h2[(size_t)(row0 + r1) * HH + k1];
    const float* A2 = &g_h2[(size_t)(row0 + r2) * HH + k2];
    int bk1 = tid / 25, bj1 = (tid % 25) * 4;
    int bk2 = (tid + 320) / 25, bj2 = ((tid + 320) % 25) * 4;
    unsigned d1b0 = smem_u32(&Bs[0][bk1][bj1]);
    unsigned d1b1 = smem_u32(&Bs[1][bk1][bj1]);
    unsigned d2b0 = smem_u32(&Bs[0][bk2][bj2]);
    unsigned d2b1 = smem_u32(&Bs[1][bk2][bj2]);

    u64 acc[4][5];
    u64 z2 = pack2(0.f, 0.f);
#pragma unroll
    for (int i = 0; i < 4; i++)
#pragma unroll
        for (int j = 0; j < 5; j++) acc[i][j] = z2;

    cpa16(d1b0, &W[bk1 * LL + bj1]);
    if (tid < 180) cpa16(d2b0, &W[bk2 * LL + bj2]);
    cpa_commit();
    float4 av1 = *(const float4*)&A1[0];
    float4 av2 = *(const float4*)&A2[0];

    for (int kt = 0; kt < 15; kt++) {
        int cur = kt & 1;
        if (kt < 14) {
            int kn = (kt + 1) * BK;
            cpa16(cur ? d1b0 : d1b1, &W[(kn + bk1) * LL + bj1]);
            if (tid < 180) cpa16(cur ? d2b0 : d2b1, &W[(kn + bk2) * LL + bj2]);
            cpa_commit();
            cpa_wait1();
        } else {
            cpa_wait0();
        }
        As[k1 + 0][r1] = av1.x;
        As[k1 + 1][r1] = av1.y;
        As[k1 + 2][r1] = av1.z;
        As[k1 + 3][r1] = av1.w;
        As[k2 + 0][r2] = av2.x;
        As[k2 + 1][r2] = av2.y;
        As[k2 + 2][r2] = av2.z;
        As[k2 + 3][r2] = av2.w;
        __syncthreads();
        if (kt < 14) {
            int kn = (kt + 1) * BK;
            av1 = *(const float4*)&A1[kn];
            av2 = *(const float4*)&A2[kn];
        }
#pragma unroll
        for (int kk = 0; kk < BK; kk++) {
            ulonglong2 aA = *(const ulonglong2*)&As[kk][ty * 8];
            ulonglong2 aB = *(const ulonglong2*)&As[kk][ty * 8 + 4];
            u64 b[5];
#pragma unroll
            for (int j = 0; j < 5; j++) {
                float bv = Bs[cur][kk][tx + 20 * j];
                b[j] = pack2(bv, bv);
            }
#pragma unroll
            for (int j = 0; j < 5; j++) {
                ffma2(acc[0][j], aA.x, b[j]);
                ffma2(acc[1][j], aA.y, b[j]);
                ffma2(acc[2][j], aB.x, b[j]);
                ffma2(acc[3][j], aB.y, b[j]);
            }
        }
        __syncthreads();
    }

    // thread-local max over its 8 contiguous rows (half a 16-edge node group)
#pragma unroll
    for (int j = 0; j < 5; j++) {
        int col = tx + 20 * j;
        float2 v0 = unpack2(acc[0][j]);
        float2 v1 = unpack2(acc[1][j]);
        float2 v2 = unpack2(acc[2][j]);
        float2 v3 = unpack2(acc[3][j]);
        float m = fmaxf(fmaxf(fmaxf(v0.x, v0.y), fmaxf(v1.x, v1.y)),
                        fmaxf(fmaxf(v2.x, v2.y), fmaxf(v3.x, v3.y)));
        red[ty][col] = m;
    }
    __syncthreads();
    if (ty < 8) {
#pragma unroll
        for (int j = 0; j < 5; j++) {
            int col = tx + 20 * j;
            float m = fmaxf(red[2 * ty][col], red[2 * ty + 1][col]);
            g_node[(n0 + ty) * LL + col] = fmaxf(m + bias[col], 0.f);
        }
    }
}

// ---------------------------------------------------------------------------
// pool: per-graph (3200 consecutive nodes) sum / mean / max over g_node[N,100]
__global__ void pool_kernel() {
    __shared__ float ssum[8][100];
    __shared__ float smax[8][100];
    int g = blockIdx.x;
    int col = threadIdx.x % 100;
    int part = threadIdx.x / 100;
    float s = 0.f, m = -CUDART_INF_F;
    int base = g * 3200 + part * 400;
    for (int n = 0; n < 400; n++) {
        float v = g_node[(base + n) * LL + col];
        s += v;
        m = fmaxf(m, v);
    }
    ssum[part][col] = s;
    smax[part][col] = m;
    __syncthreads();
    if (part == 0) {
        for (int p = 1; p < 8; p++) {
            s += ssum[p][col];
            m = fmaxf(m, smax[p][col]);
        }
        g_pooled[g * 300 + col] = s;
        g_pooled[g * 300 + 100 + col] = s / 3200.0f;
        g_pooled[g * 300 + 200 + col] = m;
    }
}

// ---------------------------------------------------------------------------
// head MLP: [8,300] -> relu 100 -> relu 100 -> 1. One block, 128 threads.
__global__ void final_kernel(const float* __restrict__ W1, const float* __restrict__ b1,
                             const float* __restrict__ W2, const float* __restrict__ b2,
                             const float* __restrict__ W3, const float* __restrict__ b3,
                             float* __restrict__ out) {
    __shared__ float sp[GB * 300];
    __shared__ float t1[GB * 100];
    int j = threadIdx.x;
    for (int i = j; i < GB * 300; i += blockDim.x) sp[i] = g_pooled[i];
    __syncthreads();

    if (j < 100) {
        float acc[GB];
#pragma unroll
        for (int r = 0; r < GB; r++) acc[r] = b1[j];
        for (int k = 0; k < 300; k++) {
            float w = W1[k * 100 + j];
#pragma unroll
            for (int r = 0; r < GB; r++) acc[r] = fmaf(sp[r * 300 + k], w, acc[r]);
        }
#pragma unroll
        for (int r = 0; r < GB; r++) t1[r * 100 + j] = fmaxf(acc[r], 0.f);
    }
    __syncthreads();

    float acc2[GB];
    if (j < 100) {
#pragma unroll
        for (int r = 0; r < GB; r++) acc2[r] = b2[j];
        for (int k = 0; k < 100; k++) {
            float w = W2[k * 100 + j];
#pragma unroll
            for (int r = 0; r < GB; r++) acc2[r] = fmaf(t1[r * 100 + k], w, acc2[r]);
        }
    }
    __syncthreads();
    if (j < 100) {
#pragma unroll
        for (int r = 0; r < GB; r++) sp[r * 100 + j] = fmaxf(acc2[r], 0.f);
    }
    __syncthreads();

    if (j < GB) {
        float s = b3[0];
        for (int k = 0; k < 100; k++) s = fmaf(sp[j * 100 + k], W3[k], s);
        out[j] = s;
    }
}

// ---------------------------------------------------------------------------
extern "C" void kernel_launch(void* const* d_in, const int* in_sizes, int n_in,
                              void* d_out, int out_size) {
    const float* x        = (const float*)d_in[0];
    const int*   eidx     = (const int*)d_in[1];   // [2,E]: row0=src, row1=dst
    const float* l0_W1 = (const float*)d_in[3];
    const float* l0_b1 = (const float*)d_in[4];
    const float* l0_W2 = (const float*)d_in[5];
    const float* l0_b2 = (const float*)d_in[6];
    const float* l0_W3 = (const float*)d_in[7];
    const float* l0_b3 = (const float*)d_in[8];
    const float* l1_W1 = (const float*)d_in[9];
    const float* l1_b1 = (const float*)d_in[10];
    const float* l1_W2 = (const float*)d_in[11];
    const float* l1_b2 = (const float*)d_in[12];
    const float* l1_W3 = (const float*)d_in[13];
    const float* l1_b3 = (const float*)d_in[14];
    const float* lin_W1 = (const float*)d_in[15];
    const float* lin_b1 = (const float*)d_in[16];
    const float* lin_W2 = (const float*)d_in[17];
    const float* lin_b2 = (const float*)d_in[18];
    const float* lin_W3 = (const float*)d_in[19];
    const float* lin_b3 = (const float*)d_in[20];

    const int* src = eidx;  // first row of edge_index

    // ---- layer 0 ----
    front_kernel<<<NN / 16, 300>>>(x, FF, l0_W1, l0_b1, 0);
    gemm_mid<<<dim3(3, EE / 128), 320>>>(src, l0_W2, l0_b2);
    gemm_out<<<EE / 128, 320>>>(l0_W3, l0_b3);
    // ---- layer 1 ----
    front_kernel<<<NN / 16, 300>>>(nullptr, LL, l1_W1, l1_b1, 1);
    gemm_mid<<<dim3(3, EE / 128), 320>>>(src, l1_W2, l1_b2);
    gemm_out<<<EE / 128, 320>>>(l1_W3, l1_b3);
    // ---- pooling + head ----
    pool_kernel<<<GB, 800>>>();
    final_kernel<<<1, 128>>>(lin_W1, lin_b1, lin_W2, lin_b2, lin_W3, lin_b3,
                             (float*)d_out);
}

// round 11
// speedup vs baseline: 3.1489x; 1.3491x over previous
#include <cuda_runtime.h>
#include <cuda_bf16.h>
#include <math_constants.h>
#include <cstdint>

#define NN 25600
#define EE 409600
#define GB 8
#define FF 7
#define HH 300
#define LL 100

// dynamic smem layout (per CTA)
#define SOFF_AH   0        // A hi  [128 rows][64 k] bf16, 128B rows, SW128
#define SOFF_AL   16384    // A lo
#define SOFF_BH   32768    // B hi  [128 n-rows][64 k] bf16
#define SOFF_BL   49152    // B lo
#define SOFF_SRC  65536    // int[128]
#define SMEMTC    66064

// ---------------- scratch (static device globals; no runtime allocation) ----
__device__ float    g_P[NN * HH];
__device__ float    g_Q[NN * HH];
__device__ uint32_t g_h2hl[(size_t)EE * HH];       // packed (hi|lo<<16) bf16 pair
__device__ float    g_node[NN * LL];
__device__ float    g_pooled[GB * 3 * LL];
// pre-split / transposed / padded weights: B[n][k] = W[k][n], [slabs][128][320]
__device__ __nv_bfloat16 g_W2h[2][3 * 128 * 320];
__device__ __nv_bfloat16 g_W2l[2][3 * 128 * 320];
__device__ __nv_bfloat16 g_W3h[2][128 * 320];
__device__ __nv_bfloat16 g_W3l[2][128 * 320];

// ---------------- PTX helpers (all baseline compute_103 instructions) -------
__device__ __forceinline__ uint32_t smem_u32(const void* p) {
    uint32_t a;
    asm("{ .reg .u64 t; cvta.to.shared.u64 t, %1; cvt.u32.u64 %0, t; }"
        : "=r"(a) : "l"(p));
    return a;
}
__device__ __forceinline__ uint32_t sw128(uint32_t o) {
    return o ^ ((o >> 3) & 0x70);
}
// cvt.rn.bf16x2.f32 d, a, b : d.hi = bf16(a), d.lo = bf16(b)
__device__ __forceinline__ uint32_t bf2pack(float hi, float lo) {
    uint32_t r;
    asm("cvt.rn.bf16x2.f32 %0, %1, %2;" : "=r"(r) : "f"(hi), "f"(lo));
    return r;
}
__device__ __forceinline__ void ldsm4(uint32_t addr, uint32_t* r) {
    asm volatile("ldmatrix.sync.aligned.m8n8.x4.shared.b16 {%0,%1,%2,%3}, [%4];"
                 : "=r"(r[0]), "=r"(r[1]), "=r"(r[2]), "=r"(r[3]) : "r"(addr));
}
__device__ __forceinline__ void mma16816(float* d, const uint32_t* a,
                                         uint32_t b0, uint32_t b1) {
    asm volatile(
        "mma.sync.aligned.m16n8k16.row.col.f32.bf16.bf16.f32 "
        "{%0,%1,%2,%3}, {%4,%5,%6,%7}, {%8,%9}, {%0,%1,%2,%3};"
        : "+f"(d[0]), "+f"(d[1]), "+f"(d[2]), "+f"(d[3])
        : "r"(a[0]), "r"(a[1]), "r"(a[2]), "r"(a[3]), "r"(b0), "r"(b1));
}

// ---------------------------------------------------------------------------
// split weights into bf16 hi/lo planes, transposed to B[n][k], padded to
// [slabs][128 n][320 k] with zeros. One block per (slab,n), 320 threads (k).
__global__ void split_w(const float* __restrict__ W,
                        __nv_bfloat16* __restrict__ oh,
                        __nv_bfloat16* __restrict__ ol,
                        int K, int Ncols) {
    int b = blockIdx.x;
    int n_local = b & 127;
    int slab = b >> 7;
    int k = threadIdx.x;
    int n = slab * 100 + n_local;
    float v = 0.f;
    if (n_local < 100 && k < K && n < Ncols) v = W[k * Ncols + n];
    __nv_bfloat16 h = __float2bfloat16(v);
    __nv_bfloat16 l = __float2bfloat16(v - __bfloat162float(h));
    oh[b * 320 + k] = h;
    ol[b * 320 + k] = l;
}

// ---------------------------------------------------------------------------
// front: per-node first MLP layer, exploiting linearity of concat([x_i, x_j-x_i]).
__global__ void front_kernel(const float* __restrict__ xin, int K,
                             const float* __restrict__ W,
                             const float* __restrict__ b,
                             int from_node) {
    __shared__ float xs[16 * 100];
    const float* __restrict__ x = from_node ? g_node : xin;
    int n0 = blockIdx.x * 16;
    int j = threadIdx.x;
    for (int i = threadIdx.x; i < 16 * K; i += 300)
        xs[i] = x[n0 * K + i];
    __syncthreads();

    float accP[16], accQ[16];
    float bj = b[j];
#pragma unroll
    for (int r = 0; r < 16; r++) { accP[r] = bj; accQ[r] = 0.f; }
    for (int k = 0; k < K; k++) {
        float wa = W[k * HH + j];
        float wb = W[(K + k) * HH + j];
        float d = wa - wb;
#pragma unroll
        for (int r = 0; r < 16; r++) {
            float xv = xs[r * K + k];
            accP[r] = fmaf(xv, d, accP[r]);
            accQ[r] = fmaf(xv, wb, accQ[r]);
        }
    }
#pragma unroll
    for (int r = 0; r < 16; r++) {
        g_P[(n0 + r) * HH + j] = accP[r];
        g_Q[(n0 + r) * HH + j] = accQ[r];
    }
}

// ---------------------------------------------------------------------------
// Core warp-MMA compute over one 64-k chunk already staged in smem.
// 8 warps: mw = wid%4 (M block of 32), nw = wid/4 (N block of 64).
// acc[mt][nt][4]: mt in {0,1} (m16 tiles), nt in 0..7 (n8 tiles).
__device__ __forceinline__ void mma_chunk(uint32_t sb, int lane, int mw, int nw,
                                          float acc[2][8][4]) {
    int arow = mw * 32 + (lane & 15);
    int akb = (lane >> 4) * 16;
    int bn = nw * 64 + (lane & 7) + ((lane >> 4) << 3);
    int bkb = ((lane >> 3) & 1) * 16;
#pragma unroll
    for (int s = 0; s < 4; s++) {
        uint32_t ah[2][4], al[2][4];
#pragma unroll
        for (int mt = 0; mt < 2; mt++) {
            uint32_t off = sw128((uint32_t)((arow + mt * 16) * 128 + akb + s * 32));
            ldsm4(sb + SOFF_AH + off, ah[mt]);
            ldsm4(sb + SOFF_AL + off, al[mt]);
        }
        uint32_t bb[4][4];
        // pass 1+2: B = hi plane, A = hi and lo
#pragma unroll
        for (int p = 0; p < 4; p++) {
            uint32_t off = sw128((uint32_t)((bn + p * 16) * 128 + bkb + s * 32));
            ldsm4(sb + SOFF_BH + off, bb[p]);
        }
#pragma unroll
        for (int mt = 0; mt < 2; mt++)
#pragma unroll
            for (int p = 0; p < 4; p++) {
                mma16816(acc[mt][2 * p + 0], ah[mt], bb[p][0], bb[p][1]);
                mma16816(acc[mt][2 * p + 1], ah[mt], bb[p][2], bb[p][3]);
                mma16816(acc[mt][2 * p + 0], al[mt], bb[p][0], bb[p][1]);
                mma16816(acc[mt][2 * p + 1], al[mt], bb[p][2], bb[p][3]);
            }
        // pass 3: B = lo plane, A = hi
#pragma unroll
        for (int p = 0; p < 4; p++) {
            uint32_t off = sw128((uint32_t)((bn + p * 16) * 128 + bkb + s * 32));
            ldsm4(sb + SOFF_BL + off, bb[p]);
        }
#pragma unroll
        for (int mt = 0; mt < 2; mt++)
#pragma unroll
            for (int p = 0; p < 4; p++) {
                mma16816(acc[mt][2 * p + 0], ah[mt], bb[p][0], bb[p][1]);
                mma16816(acc[mt][2 * p + 1], ah[mt], bb[p][2], bb[p][3]);
            }
    }
}

// ---------------------------------------------------------------------------
// gemm_mid_mma: h2[128 edges, 100-col slab] = relu(relu(P+Q) @ W2 + b2),
// bf16 3-pass split via mma.sync, fp32 register accum.
// Output stored to g_h2hl as packed bf16 (hi | lo<<16).
__global__ __launch_bounds__(256, 2)
void gemm_mid_mma(const int* __restrict__ src,
                  const __nv_bfloat16* __restrict__ Bh_g,
                  const __nv_bfloat16* __restrict__ Bl_g,
                  const float* __restrict__ bias) {
    extern __shared__ char smem[];
    uint32_t sb = smem_u32(smem);
    int tid = threadIdx.x, wid = tid >> 5, lane = tid & 31;
    int mw = wid & 3, nw = wid >> 2;
    int slab = blockIdx.x;
    int row0 = blockIdx.y * 128;
    int n0 = blockIdx.y * 8;
    int* s_src = (int*)(smem + SOFF_SRC);

    if (tid < 128) s_src[tid] = src[row0 + tid];
    __syncthreads();

    const __nv_bfloat16* bhp = Bh_g + slab * (128 * 320);
    const __nv_bfloat16* blp = Bl_g + slab * (128 * 320);

    float acc[2][8][4];
#pragma unroll
    for (int mt = 0; mt < 2; mt++)
#pragma unroll
        for (int nt = 0; nt < 8; nt++)
#pragma unroll
            for (int e = 0; e < 4; e++) acc[mt][nt][e] = 0.f;

    for (int ch = 0; ch < 5; ch++) {
        int k0 = ch * 64;
        // A tile: gather relu(P+Q), split hi/lo, swizzled STS
        for (int i = tid; i < 2048; i += 256) {
            int row = i >> 4, kq = i & 15;
            int kg = k0 + kq * 4;
            float4 v = make_float4(0.f, 0.f, 0.f, 0.f);
            if (kg < 300) {
                float4 p = *(const float4*)&g_P[(n0 + (row >> 4)) * HH + kg];
                float4 q = *(const float4*)&g_Q[s_src[row] * HH + kg];
                v.x = fmaxf(p.x + q.x, 0.f);
                v.y = fmaxf(p.y + q.y, 0.f);
                v.z = fmaxf(p.z + q.z, 0.f);
                v.w = fmaxf(p.w + q.w, 0.f);
            }
            uint32_t h01 = bf2pack(v.y, v.x);
            uint32_t h23 = bf2pack(v.w, v.z);
            float l0 = v.x - __uint_as_float(h01 << 16);
            float l1 = v.y - __uint_as_float(h01 & 0xFFFF0000u);
            float l2 = v.z - __uint_as_float(h23 << 16);
            float l3 = v.w - __uint_as_float(h23 & 0xFFFF0000u);
            uint32_t q01 = bf2pack(l1, l0);
            uint32_t q23 = bf2pack(l3, l2);
            uint32_t o = sw128((uint32_t)(row * 128 + kq * 8));
            *(uint2*)(smem + SOFF_AH + o) = make_uint2(h01, h23);
            *(uint2*)(smem + SOFF_AL + o) = make_uint2(q01, q23);
        }
        // B tiles (both planes) from pre-split global
        for (int i = tid; i < 4096; i += 256) {
            int pl = i >= 2048;
            int j = i & 2047;
            int n = j >> 4, kq = j & 15;
            uint2 w = *(const uint2*)((pl ? blp : bhp) + n * 320 + k0 + kq * 4);
            uint32_t o = sw128((uint32_t)(n * 128 + kq * 8));
            *(uint2*)(smem + (pl ? SOFF_BL : SOFF_BH) + o) = w;
        }
        __syncthreads();
        mma_chunk(sb, lane, mw, nw, acc);
        __syncthreads();
    }

    // epilogue: bias + relu + bf16 hi/lo pack -> stage -> global
    uint32_t* stage = (uint32_t*)smem;   // [128][104] u32 overlays tiles
    float bload[2];
#pragma unroll
    for (int mt = 0; mt < 2; mt++)
#pragma unroll
        for (int nt = 0; nt < 8; nt++) {
            int c = nw * 64 + nt * 8 + (lane & 3) * 2;
            int r0 = mw * 32 + mt * 16 + (lane >> 2);
#pragma unroll
            for (int e = 0; e < 4; e++) {
                int cc = c + (e & 1);
                int rr = (e < 2) ? r0 : r0 + 8;
                if (cc < 100) {
                    float v = fmaxf(acc[mt][nt][e] + bias[slab * 100 + cc], 0.f);
                    __nv_bfloat16 hh = __float2bfloat16(v);
                    __nv_bfloat16 ll = __float2bfloat16(v - __bfloat162float(hh));
                    stage[rr * 104 + cc] =
                        ((uint32_t)__bfloat16_as_ushort(ll) << 16) |
                        __bfloat16_as_ushort(hh);
                }
                (void)bload;
            }
        }
    __syncthreads();
    for (int i = tid; i < 12800; i += 256) {
        int row = i / 100, c = i - row * 100;
        g_h2hl[(size_t)(row0 + row) * HH + slab * 100 + c] = stage[row * 104 + c];
    }
}

// ---------------------------------------------------------------------------
// gemm_out_mma: h3 = h2 @ W3 (bf16 split), fused max over 16-edge groups,
// +b3, relu -> g_node.
__global__ __launch_bounds__(256, 2)
void gemm_out_mma(const __nv_bfloat16* __restrict__ Bh_g,
                  const __nv_bfloat16* __restrict__ Bl_g,
                  const float* __restrict__ bias) {
    extern __shared__ char smem[];
    uint32_t sb = smem_u32(smem);
    int tid = threadIdx.x, wid = tid >> 5, lane = tid & 31;
    int mw = wid & 3, nw = wid >> 2;
    int row0 = blockIdx.x * 128;
    int n0 = blockIdx.x * 8;

    float acc[2][8][4];
#pragma unroll
    for (int mt = 0; mt < 2; mt++)
#pragma unroll
        for (int nt = 0; nt < 8; nt++)
#pragma unroll
            for (int e = 0; e < 4; e++) acc[mt][nt][e] = 0.f;

    for (int ch = 0; ch < 5; ch++) {
        int k0 = ch * 64;
        // A tile from packed h2 planes
        for (int i = tid; i < 2048; i += 256) {
            int row = i >> 4, kq = i & 15;
            int kg = k0 + kq * 4;
            uint4 t = make_uint4(0u, 0u, 0u, 0u);
            if (kg < 300)
                t = *(const uint4*)&g_h2hl[(size_t)(row0 + row) * HH + kg];
            uint32_t h01 = __byte_perm(t.x, t.y, 0x5410);
            uint32_t h23 = __byte_perm(t.z, t.w, 0x5410);
            uint32_t l01 = __byte_perm(t.x, t.y, 0x7632);
            uint32_t l23 = __byte_perm(t.z, t.w, 0x7632);
            uint32_t o = sw128((uint32_t)(row * 128 + kq * 8));
            *(uint2*)(smem + SOFF_AH + o) = make_uint2(h01, h23);
            *(uint2*)(smem + SOFF_AL + o) = make_uint2(l01, l23);
        }
        for (int i = tid; i < 4096; i += 256) {
            int pl = i >= 2048;
            int j = i & 2047;
            int n = j >> 4, kq = j & 15;
            uint2 w = *(const uint2*)((pl ? Bl_g : Bh_g) + n * 320 + k0 + kq * 4);
            uint32_t o = sw128((uint32_t)(n * 128 + kq * 8));
            *(uint2*)(smem + (pl ? SOFF_BL : SOFF_BH) + o) = w;
        }
        __syncthreads();
        mma_chunk(sb, lane, mw, nw, acc);
        __syncthreads();
    }

    // epilogue: stage fp32, then max over 16-edge groups + bias + relu
    float* stagef = (float*)smem;        // [128][104] fp32 overlays tiles
#pragma unroll
    for (int mt = 0; mt < 2; mt++)
#pragma unroll
        for (int nt = 0; nt < 8; nt++) {
            int c = nw * 64 + nt * 8 + (lane & 3) * 2;
            int r0 = mw * 32 + mt * 16 + (lane >> 2);
#pragma unroll
            for (int e = 0; e < 4; e++) {
                int cc = c + (e & 1);
                int rr = (e < 2) ? r0 : r0 + 8;
                if (cc < 100) stagef[rr * 104 + cc] = acc[mt][nt][e];
            }
        }
    __syncthreads();
    for (int i = tid; i < 800; i += 256) {
        int n = i / 100, c = i - n * 100;
        float m = -CUDART_INF_F;
#pragma unroll
        for (int rr = 0; rr < 16; rr++)
            m = fmaxf(m, stagef[(n * 16 + rr) * 104 + c]);
        g_node[(n0 + n) * LL + c] = fmaxf(m + bias[c], 0.f);
    }
}

// ---------------------------------------------------------------------------
__global__ void pool_kernel() {
    __shared__ float ssum[8][100];
    __shared__ float smax[8][100];
    int g = blockIdx.x;
    int col = threadIdx.x % 100;
    int part = threadIdx.x / 100;
    float s = 0.f, m = -CUDART_INF_F;
    int base = g * 3200 + part * 400;
    for (int n = 0; n < 400; n++) {
        float v = g_node[(base + n) * LL + col];
        s += v;
        m = fmaxf(m, v);
    }
    ssum[part][col] = s;
    smax[part][col] = m;
    __syncthreads();
    if (part == 0) {
        for (int p = 1; p < 8; p++) {
            s += ssum[p][col];
            m = fmaxf(m, smax[p][col]);
        }
        g_pooled[g * 300 + col] = s;
        g_pooled[g * 300 + 100 + col] = s / 3200.0f;
        g_pooled[g * 300 + 200 + col] = m;
    }
}

__global__ void final_kernel(const float* __restrict__ W1, const float* __restrict__ b1,
                             const float* __restrict__ W2, const float* __restrict__ b2,
                             const float* __restrict__ W3, const float* __restrict__ b3,
                             float* __restrict__ out) {
    __shared__ float sp[GB * 300];
    __shared__ float t1[GB * 100];
    int j = threadIdx.x;
    for (int i = j; i < GB * 300; i += blockDim.x) sp[i] = g_pooled[i];
    __syncthreads();
    if (j < 100) {
        float acc[GB];
#pragma unroll
        for (int r = 0; r < GB; r++) acc[r] = b1[j];
        for (int k = 0; k < 300; k++) {
            float w = W1[k * 100 + j];
#pragma unroll
            for (int r = 0; r < GB; r++) acc[r] = fmaf(sp[r * 300 + k], w, acc[r]);
        }
#pragma unroll
        for (int r = 0; r < GB; r++) t1[r * 100 + j] = fmaxf(acc[r], 0.f);
    }
    __syncthreads();
    float acc2[GB];
    if (j < 100) {
#pragma unroll
        for (int r = 0; r < GB; r++) acc2[r] = b2[j];
        for (int k = 0; k < 100; k++) {
            float w = W2[k * 100 + j];
#pragma unroll
            for (int r = 0; r < GB; r++) acc2[r] = fmaf(t1[r * 100 + k], w, acc2[r]);
        }
    }
    __syncthreads();
    if (j < 100) {
#pragma unroll
        for (int r = 0; r < GB; r++) sp[r * 100 + j] = fmaxf(acc2[r], 0.f);
    }
    __syncthreads();
    if (j < GB) {
        float s = b3[0];
        for (int k = 0; k < 100; k++) s = fmaf(sp[j * 100 + k], W3[k], s);
        out[j] = s;
    }
}

// ---------------------------------------------------------------------------
extern "C" void kernel_launch(void* const* d_in, const int* in_sizes, int n_in,
                              void* d_out, int out_size) {
    const float* x     = (const float*)d_in[0];
    const int*   eidx  = (const int*)d_in[1];
    const float* l0_W1 = (const float*)d_in[3];
    const float* l0_b1 = (const float*)d_in[4];
    const float* l0_W2 = (const float*)d_in[5];
    const float* l0_b2 = (const float*)d_in[6];
    const float* l0_W3 = (const float*)d_in[7];
    const float* l0_b3 = (const float*)d_in[8];
    const float* l1_W1 = (const float*)d_in[9];
    const float* l1_b1 = (const float*)d_in[10];
    const float* l1_W2 = (const float*)d_in[11];
    const float* l1_b2 = (const float*)d_in[12];
    const float* l1_W3 = (const float*)d_in[13];
    const float* l1_b3 = (const float*)d_in[14];
    const float* lin_W1 = (const float*)d_in[15];
    const float* lin_b1 = (const float*)d_in[16];
    const float* lin_W2 = (const float*)d_in[17];
    const float* lin_b2 = (const float*)d_in[18];
    const float* lin_W3 = (const float*)d_in[19];
    const float* lin_b3 = (const float*)d_in[20];

    const int* src = eidx;

    cudaFuncSetAttribute(gemm_mid_mma, cudaFuncAttributeMaxDynamicSharedMemorySize, SMEMTC);
    cudaFuncSetAttribute(gemm_out_mma, cudaFuncAttributeMaxDynamicSharedMemorySize, SMEMTC);

    __nv_bfloat16 *w2h0, *w2l0, *w2h1, *w2l1, *w3h0, *w3l0, *w3h1, *w3l1;
    cudaGetSymbolAddress((void**)&w2h0, g_W2h);
    cudaGetSymbolAddress((void**)&w2l0, g_W2l);
    cudaGetSymbolAddress((void**)&w3h0, g_W3h);
    cudaGetSymbolAddress((void**)&w3l0, g_W3l);
    w2h1 = w2h0 + 3 * 128 * 320; w2l1 = w2l0 + 3 * 128 * 320;
    w3h1 = w3h0 + 128 * 320;     w3l1 = w3l0 + 128 * 320;

    // weight prep (tiny)
    split_w<<<3 * 128, 320>>>(l0_W2, w2h0, w2l0, 300, 300);
    split_w<<<128, 320>>>(l0_W3, w3h0, w3l0, 300, 100);
    split_w<<<3 * 128, 320>>>(l1_W2, w2h1, w2l1, 300, 300);
    split_w<<<128, 320>>>(l1_W3, w3h1, w3l1, 300, 100);

    // ---- layer 0 ----
    front_kernel<<<NN / 16, 300>>>(x, FF, l0_W1, l0_b1, 0);
    gemm_mid_mma<<<dim3(3, EE / 128), 256, SMEMTC>>>(src, w2h0, w2l0, l0_b2);
    gemm_out_mma<<<EE / 128, 256, SMEMTC>>>(w3h0, w3l0, l0_b3);
    // ---- layer 1 ----
    front_kernel<<<NN / 16, 300>>>(nullptr, LL, l1_W1, l1_b1, 1);
    gemm_mid_mma<<<dim3(3, EE / 128), 256, SMEMTC>>>(src, w2h1, w2l1, l1_b2);
    gemm_out_mma<<<EE / 128, 256, SMEMTC>>>(w3h1, w3l1, l1_b3);
    // ---- pooling + head ----
    pool_kernel<<<GB, 800>>>();
    final_kernel<<<1, 128>>>(lin_W1, lin_b1, lin_W2, lin_b2, lin_W3, lin_b3,
                             (float*)d_out);
}